// round 12
// baseline (speedup 1.0000x reference)
#include <cuda_runtime.h>
#include <cuda_bf16.h>

// GroupedEmbeddingBag, R7 (5th retry after infra timeouts): FLAT POSITION
// DECOMPOSITION. Each warp owns 64 contiguous positions of one table's
// values[] (perfectly balanced; L % 64 == 0). Lane l holds indices for
// positions base+l and base+32+l and the binary-searched segment (bag) ids
// for both. Mainloop: 16 batches of 4 independent 512B row gathers (indices
// via shfl broadcast), accumulating into a register float4; on segment change
// (avg ~4x/warp) the partial is flushed via atomicAdd (REDG) onto pre-zeroed
// out. No smem, no barriers in the gather kernel. t-major warp order keeps
// the active table (102MB) + out (16.8MB) L2-resident.

#define T_TABLES 8
#define N_ROWS   200000
#define D_DIM    128
#define B_BAGS   8192
#define L_IDX    163840
#define WPOS     64                       // positions per warp
#define RANGES_PER_TABLE (L_IDX / WPOS)   // 2560
#define OUT_ELEMS (B_BAGS * T_TABLES * D_DIM)

__global__ void zero_out_kernel(float4* __restrict__ out4)
{
    const int n4 = OUT_ELEMS / 4;         // 2,097,152
    for (int i = blockIdx.x * blockDim.x + threadIdx.x; i < n4;
         i += gridDim.x * blockDim.x)
        out4[i] = make_float4(0.f, 0.f, 0.f, 0.f);
}

__global__ __launch_bounds__(128)
void grouped_embedding_bag_kernel(const float*  __restrict__ weights,
                                  const int*    __restrict__ values,
                                  const int*    __restrict__ offsets,
                                  float*        __restrict__ out)
{
    const int warp_global = (blockIdx.x << 2) + (threadIdx.x >> 5);
    const int lane = threadIdx.x & 31;

    const int t = warp_global / RANGES_PER_TABLE;   // t-major: table locality
    const int r = warp_global - t * RANGES_PER_TABLE;
    const int base = r * WPOS;                      // position range [base, base+64)

    const int* __restrict__ vals_t = values + (size_t)t * L_IDX;
    const int* __restrict__ offs_t = offsets + t * (B_BAGS + 1);
    const float4* __restrict__ wbase =
        reinterpret_cast<const float4*>(weights + (size_t)t * N_ROWS * D_DIM) + lane;

    // Per-lane: indices for my two positions (coalesced 128B loads).
    const int p0 = base + lane;
    const int p1 = base + 32 + lane;
    const int id0 = __ldg(vals_t + p0);
    const int id1 = __ldg(vals_t + p1);

    // Per-lane: segment (bag) ids via two interleaved binary searches.
    // seg(p) = m-1, m = first index in [1, B] with offs_t[m] > p
    // (offs_t[B] = L > p always, so hi = B is a valid bracket).
    int lo0 = 1, hi0 = B_BAGS, lo1 = 1, hi1 = B_BAGS;
    #pragma unroll
    for (int it = 0; it < 13; ++it) {               // ceil(log2(8192)) = 13
        if (lo0 < hi0) {
            const int mid = (lo0 + hi0) >> 1;
            if (__ldg(offs_t + mid) > p0) hi0 = mid; else lo0 = mid + 1;
        }
        if (lo1 < hi1) {
            const int mid = (lo1 + hi1) >> 1;
            if (__ldg(offs_t + mid) > p1) hi1 = mid; else lo1 = mid + 1;
        }
    }
    const int s0 = lo0 - 1;
    const int s1 = lo1 - 1;

    // Mainloop: 16 batches of 4 gathers; flush partial on segment change.
    float* __restrict__ out_t = out + t * D_DIM + lane * 4;   // + bag*T*D later
    float4 acc = make_float4(0.f, 0.f, 0.f, 0.f);
    int cur = __shfl_sync(0xffffffffu, s0, 0);      // seg of first position

    #pragma unroll 4
    for (int q = 0; q < 16; ++q) {
        const int j = q << 2;
        // broadcast indices for positions j..j+3 ((j&32) uniform per j)
        const int i0 = __shfl_sync(0xffffffffu, (j & 32) ? id1 : id0,  j      & 31);
        const int i1 = __shfl_sync(0xffffffffu, ((j + 1) & 32) ? id1 : id0, (j + 1) & 31);
        const int i2 = __shfl_sync(0xffffffffu, ((j + 2) & 32) ? id1 : id0, (j + 2) & 31);
        const int i3 = __shfl_sync(0xffffffffu, ((j + 3) & 32) ? id1 : id0, (j + 3) & 31);

        const float4 v0 = __ldg(wbase + (size_t)i0 * 32);
        const float4 v1 = __ldg(wbase + (size_t)i1 * 32);
        const float4 v2 = __ldg(wbase + (size_t)i2 * 32);
        const float4 v3 = __ldg(wbase + (size_t)i3 * 32);

        #pragma unroll
        for (int k = 0; k < 4; ++k) {
            const int jj = j + k;
            const int sg = __shfl_sync(0xffffffffu, (jj & 32) ? s1 : s0, jj & 31);
            if (sg != cur) {                         // warp-uniform branch
                float* o = out_t + (size_t)cur * (T_TABLES * D_DIM);
                atomicAdd(o + 0, acc.x);
                atomicAdd(o + 1, acc.y);
                atomicAdd(o + 2, acc.z);
                atomicAdd(o + 3, acc.w);
                acc = make_float4(0.f, 0.f, 0.f, 0.f);
                cur = sg;
            }
            const float4 v = (k == 0) ? v0 : (k == 1) ? v1 : (k == 2) ? v2 : v3;
            acc.x += v.x; acc.y += v.y; acc.z += v.z; acc.w += v.w;
        }
    }
    // final flush
    {
        float* o = out_t + (size_t)cur * (T_TABLES * D_DIM);
        atomicAdd(o + 0, acc.x);
        atomicAdd(o + 1, acc.y);
        atomicAdd(o + 2, acc.z);
        atomicAdd(o + 3, acc.w);
    }
}

extern "C" void kernel_launch(void* const* d_in, const int* in_sizes, int n_in,
                              void* d_out, int out_size)
{
    const float* weights = (const float*)d_in[0];  // [T, N, D] f32
    const int*   values  = (const int*)  d_in[1];  // [T, L]    i32
    const int*   offsets = (const int*)  d_in[2];  // [T, B+1]  i32
    float*       out     = (float*)d_out;          // [B, T*D]  f32

    zero_out_kernel<<<2048, 256>>>((float4*)out);

    const int total_warps = T_TABLES * RANGES_PER_TABLE;   // 20480
    const int blocks = total_warps / 4;                    // 5120 CTAs x 128 thr
    grouped_embedding_bag_kernel<<<blocks, 128>>>(weights, values, offsets, out);
}